// round 6
// baseline (speedup 1.0000x reference)
#include <cuda_runtime.h>
#include <cuda_bf16.h>
#include <cstdint>
#include <cmath>

// ---------------------------------------------------------------------------
// ResidualConvLSTM2D  (B=4, T=16, H=W=64, Cin=32, F=64)
// Round 5: bf16 split-2 implicit GEMM on warp-level mma.sync (HMMA.16816).
// (tcgen05 unavailable: harness compiles PTX at compute_103, not 103a.)
// ---------------------------------------------------------------------------

#define B_   4
#define T_   16
#define HW   4096
#define CIN_X 32
#define F_   64
#define COUT 256
#define FRAMES 64
#define KPAD_X 320        // 9*32=288 padded to 5 chunks of 64
#define KPAD_H 576        // 9*64 = 9 chunks of 64
#define MX (FRAMES * HW)  // 262144
#define MH (B_ * HW)      // 16384

typedef __nv_bfloat16 bf16;

// ------------------------- scratch (__device__ globals) ---------------------
__device__ bf16  g_Ax_hi[(size_t)MX * KPAD_X];
__device__ bf16  g_Ax_lo[(size_t)MX * KPAD_X];
__device__ bf16  g_Ah_hi[(size_t)MH * KPAD_H];
__device__ bf16  g_Ah_lo[(size_t)MH * KPAD_H];
__device__ bf16  g_Wx_hi[COUT * KPAD_X];
__device__ bf16  g_Wx_lo[COUT * KPAD_X];
__device__ bf16  g_Wh_hi[COUT * KPAD_H];
__device__ bf16  g_Wh_lo[COUT * KPAD_H];
__device__ float g_zx[(size_t)FRAMES * COUT * HW];   // [frame][oc][pix]
__device__ float g_zs[(size_t)B_ * COUT * HW];       // [b][oc][pix]
__device__ float g_c [(size_t)B_ * F_ * HW];         // [b][f][pix]
__device__ bf16  g_h_hi[(size_t)MH * F_];            // [b*HW+pix][f]
__device__ bf16  g_h_lo[(size_t)MH * F_];

// ------------------------- PTX helpers --------------------------------------
__device__ __forceinline__ uint32_t smem_u32(const void* p) {
    uint32_t a;
    asm("{ .reg .u64 t; cvta.to.shared.u64 t, %1; cvt.u32.u64 %0, t; }" : "=r"(a) : "l"(p));
    return a;
}
__device__ __forceinline__ void cp16(uint32_t dst, const void* src) {
    asm volatile("cp.async.cg.shared.global [%0], [%1], 16;" :: "r"(dst), "l"(src));
}
__device__ __forceinline__ void ldm_x4(uint32_t* r, uint32_t addr) {
    asm volatile("ldmatrix.sync.aligned.m8n8.x4.shared.b16 {%0,%1,%2,%3}, [%4];"
                 : "=r"(r[0]), "=r"(r[1]), "=r"(r[2]), "=r"(r[3]) : "r"(addr));
}
__device__ __forceinline__ void mma16816(float* c, const uint32_t* a, const uint32_t* b) {
    asm volatile("mma.sync.aligned.m16n8k16.row.col.f32.bf16.bf16.f32 "
                 "{%0,%1,%2,%3}, {%4,%5,%6,%7}, {%8,%9}, {%0,%1,%2,%3};"
                 : "+f"(c[0]), "+f"(c[1]), "+f"(c[2]), "+f"(c[3])
                 : "r"(a[0]), "r"(a[1]), "r"(a[2]), "r"(a[3]), "r"(b[0]), "r"(b[1]));
}

// ------------------------- small kernels ------------------------------------
__global__ void zero_state_kernel() {
    int g = blockIdx.x * 256 + threadIdx.x;     // 1048576 elems
    g_c[g] = 0.f;
    g_h_hi[g] = __float2bfloat16(0.f);
    g_h_lo[g] = __float2bfloat16(0.f);
}

__global__ void pack_wx_kernel(const float* __restrict__ Wx) {
    int g = blockIdx.x * 256 + threadIdx.x;     // 256*320
    int n = g / KPAD_X, k = g - n * KPAD_X;
    int tap = k >> 5, ci = k & 31;
    float v = (tap < 9) ? Wx[(tap * CIN_X + ci) * COUT + n] : 0.f;
    bf16 hi = __float2bfloat16(v);
    g_Wx_hi[g] = hi;
    g_Wx_lo[g] = __float2bfloat16(v - __bfloat162float(hi));
}

__global__ void pack_wh_kernel(const float* __restrict__ Wh) {
    int g = blockIdx.x * 256 + threadIdx.x;     // 256*576
    int n = g / KPAD_H, k = g - n * KPAD_H;
    int tap = k >> 6, ci = k & 63;
    float v = Wh[(tap * F_ + ci) * COUT + n];
    bf16 hi = __float2bfloat16(v);
    g_Wh_hi[g] = hi;
    g_Wh_lo[g] = __float2bfloat16(v - __bfloat162float(hi));
}

// im2col for x: A[m][k], k = tap*32+ci, tap 9 = zero pad. grid(1024, 10)
__global__ void im2col_x_kernel(const float* __restrict__ x) {
    int m = blockIdx.x * 256 + threadIdx.x;     // < 262144
    int tap = blockIdx.y;
    size_t dst = (size_t)m * KPAD_X + tap * 32;
    if (tap == 9) {
        bf16 z = __float2bfloat16(0.f);
        #pragma unroll
        for (int j = 0; j < 32; j++) { g_Ax_hi[dst + j] = z; g_Ax_lo[dst + j] = z; }
        return;
    }
    int frame = m >> 12, pix = m & 4095;
    int y = pix >> 6, xx = pix & 63;
    int sy = y + tap / 3 - 1, sx = xx + tap % 3 - 1;
    bool valid = (unsigned)sy < 64u && (unsigned)sx < 64u;
    const float* src = x + ((size_t)frame * HW + sy * 64 + sx) * CIN_X;
    #pragma unroll
    for (int j = 0; j < 32; j++) {
        float v = valid ? src[j] : 0.f;
        bf16 hi = __float2bfloat16(v);
        g_Ax_hi[dst + j] = hi;
        g_Ax_lo[dst + j] = __float2bfloat16(v - __bfloat162float(hi));
    }
}

// im2col for h (already bf16 split): shifted copy. grid(64, 9)
__global__ void im2col_h_kernel() {
    int m = blockIdx.x * 256 + threadIdx.x;     // < 16384
    int tap = blockIdx.y;
    int b = m >> 12, pix = m & 4095;
    int y = pix >> 6, xx = pix & 63;
    int sy = y + tap / 3 - 1, sx = xx + tap % 3 - 1;
    bool valid = (unsigned)sy < 64u && (unsigned)sx < 64u;
    size_t dst = (size_t)m * KPAD_H + tap * 64;
    if (valid) {
        size_t src = ((size_t)b * HW + sy * 64 + sx) * F_;
        const int4* sh = (const int4*)(g_h_hi + src);
        const int4* sl = (const int4*)(g_h_lo + src);
        int4* dh = (int4*)(g_Ah_hi + dst);
        int4* dl = (int4*)(g_Ah_lo + dst);
        #pragma unroll
        for (int j = 0; j < 8; j++) { dh[j] = sh[j]; dl[j] = sl[j]; }
    } else {
        int4 z = make_int4(0, 0, 0, 0);
        int4* dh = (int4*)(g_Ah_hi + dst);
        int4* dl = (int4*)(g_Ah_lo + dst);
        #pragma unroll
        for (int j = 0; j < 8; j++) { dh[j] = z; dl[j] = z; }
    }
}

// residual: out[frame][pix][f] = x @ Wp + bp  (initializes all of d_out)
__global__ void residual_kernel(const float* __restrict__ x,
                                const float* __restrict__ Wp,
                                const float* __restrict__ bp,
                                float* __restrict__ out) {
    __shared__ float sW[CIN_X * F_];
    __shared__ float sb[F_];
    for (int i = threadIdx.x; i < CIN_X * F_; i += 256) sW[i] = Wp[i];
    if (threadIdx.x < F_) sb[threadIdx.x] = bp[threadIdx.x];
    __syncthreads();
    int g = blockIdx.x * 256 + threadIdx.x;
    float xv[CIN_X];
    const float4* xp = (const float4*)(x + (size_t)g * CIN_X);
    #pragma unroll
    for (int i = 0; i < CIN_X / 4; i++) {
        float4 v = xp[i];
        xv[4*i] = v.x; xv[4*i+1] = v.y; xv[4*i+2] = v.z; xv[4*i+3] = v.w;
    }
    float* op = out + (size_t)g * F_;
    #pragma unroll 4
    for (int f = 0; f < F_; f++) {
        float a = sb[f];
        #pragma unroll
        for (int ci = 0; ci < CIN_X; ci++) a = fmaf(xv[ci], sW[ci * F_ + f], a);
        op[f] = a;
    }
}

// ------------------------- GEMM (mma.sync, bf16 split-2) --------------------
// C[m][n] = sum_k A[m][k]*B[n][k].  Block tile 128x128, 8 warps (warp 32x64),
// K chunks of 64, 2-stage cp.async pipeline.  Pad rows to 72 bf16 (144B):
// ldmatrix row addresses cycle all 8 16B bank segments -> conflict-free.
#define LDK 72
#define TILE_E (128 * LDK)        // elems per tile
#define STAGE_E (4 * TILE_E)      // Ahi, Alo, Bhi, Blo
#define SM_BYTES (2 * STAGE_E * 2)

__global__ void __launch_bounds__(256, 1)
gemm_mma_kernel(const bf16* __restrict__ Ahi, const bf16* __restrict__ Alo,
                const bf16* __restrict__ Bhi, const bf16* __restrict__ Blo,
                float* __restrict__ out, const float* __restrict__ bias,
                int kchunks, int kpad) {
    extern __shared__ bf16 sm[];
    int tid = threadIdx.x;
    size_t m0 = (size_t)blockIdx.x * 128;
    int n0 = blockIdx.y * 128;
    int lane = tid & 31, wid = tid >> 5;
    int wm = (wid & 3) * 32;          // warp m-offset in tile
    int wn = (wid >> 2) * 64;         // warp n-offset in tile

    float acc[2][8][4];
    #pragma unroll
    for (int a = 0; a < 2; a++)
        #pragma unroll
        for (int b = 0; b < 8; b++)
            #pragma unroll
            for (int r = 0; r < 4; r++) acc[a][b][r] = 0.f;

    // per-thread load slots (16 x 16B per stage)
    auto issue = [&](int c, int stage) {
        bf16* s = sm + stage * STAGE_E;
        #pragma unroll
        for (int it = 0; it < 16; it++) {
            int idx = it * 256 + tid;          // 0..4095
            int tile = idx >> 10;              // 0 Ahi,1 Alo,2 Bhi,3 Blo
            int row = (idx >> 3) & 127;
            int seg = idx & 7;                 // 8 bf16 per seg
            const bf16* src;
            if (tile == 0)      src = Ahi + (m0 + row) * (size_t)kpad + c * 64 + seg * 8;
            else if (tile == 1) src = Alo + (m0 + row) * (size_t)kpad + c * 64 + seg * 8;
            else if (tile == 2) src = Bhi + (size_t)(n0 + row) * kpad + c * 64 + seg * 8;
            else                src = Blo + (size_t)(n0 + row) * kpad + c * 64 + seg * 8;
            cp16(smem_u32(s + tile * TILE_E + row * LDK + seg * 8), src);
        }
        asm volatile("cp.async.commit_group;" ::: "memory");
    };

    issue(0, 0);
    for (int c = 0; c < kchunks; c++) {
        int stage = c & 1;
        if (c + 1 < kchunks) {
            issue(c + 1, (c + 1) & 1);
            asm volatile("cp.async.wait_group 1;" ::: "memory");
        } else {
            asm volatile("cp.async.wait_group 0;" ::: "memory");
        }
        __syncthreads();

        bf16* s = sm + stage * STAGE_E;
        uint32_t sAhi = smem_u32(s);
        uint32_t sAlo = sAhi + TILE_E * 2;
        uint32_t sBhi = sAhi + 2 * TILE_E * 2;
        uint32_t sBlo = sAhi + 3 * TILE_E * 2;

        #pragma unroll
        for (int ks = 0; ks < 4; ks++) {
            int k0 = ks * 16;
            uint32_t ahi[2][4], alo[2][4];
            #pragma unroll
            for (int mf = 0; mf < 2; mf++) {
                int row = wm + mf * 16 + (lane & 15);
                int col = k0 + (lane >> 4) * 8;
                ldm_x4(ahi[mf], sAhi + (row * LDK + col) * 2);
                ldm_x4(alo[mf], sAlo + (row * LDK + col) * 2);
            }
            uint32_t bhi[4][4], blo[4][4];
            #pragma unroll
            for (int g = 0; g < 4; g++) {
                int row = wn + g * 16 + (lane & 7) + ((lane >> 4) << 3);
                int col = k0 + ((lane >> 3) & 1) * 8;
                ldm_x4(bhi[g], sBhi + (row * LDK + col) * 2);
                ldm_x4(blo[g], sBlo + (row * LDK + col) * 2);
            }
            #pragma unroll
            for (int mf = 0; mf < 2; mf++) {
                #pragma unroll
                for (int g = 0; g < 4; g++) {
                    mma16816(acc[mf][2*g  ], ahi[mf], &bhi[g][0]);
                    mma16816(acc[mf][2*g  ], ahi[mf], &blo[g][0]);
                    mma16816(acc[mf][2*g  ], alo[mf], &bhi[g][0]);
                    mma16816(acc[mf][2*g+1], ahi[mf], &bhi[g][2]);
                    mma16816(acc[mf][2*g+1], ahi[mf], &blo[g][2]);
                    mma16816(acc[mf][2*g+1], alo[mf], &bhi[g][2]);
                }
            }
        }
        __syncthreads();
    }

    // epilogue: C[m][n] -> out[frame][oc][pix] (+bias)
    #pragma unroll
    for (int mf = 0; mf < 2; mf++) {
        #pragma unroll
        for (int nf = 0; nf < 8; nf++) {
            #pragma unroll
            for (int half = 0; half < 2; half++) {
                size_t m = m0 + wm + mf * 16 + (lane >> 2) + half * 8;
                int n = n0 + wn + nf * 8 + (lane & 3) * 2;
                size_t base = ((m >> 12) * COUT) * (size_t)HW + (m & 4095);
                float v0 = acc[mf][nf][half * 2];
                float v1 = acc[mf][nf][half * 2 + 1];
                if (bias) { v0 += bias[n]; v1 += bias[n + 1]; }
                out[base + ((size_t)n << 12)] = v0;
                out[base + ((size_t)(n + 1) << 12)] = v1;
            }
        }
    }
}

// ------------------------- gates --------------------------------------------
__global__ void gate_kernel(float* __restrict__ out, int t) {
    int g = blockIdx.x * 256 + threadIdx.x;     // < 16384 : (b, pix)
    int b = g >> 12, pix = g & 4095;
    int frame = b * T_ + t;
    size_t zxb = ((size_t)frame << 20) + pix;
    size_t zsb = ((size_t)b << 20) + pix;
    size_t cb  = (((size_t)b * F_) << 12) + pix;
    float* op = out + ((((size_t)frame << 12) + pix) * F_);
    bf16* hh = g_h_hi + (size_t)g * F_;
    bf16* hl = g_h_lo + (size_t)g * F_;

    #pragma unroll 4
    for (int f = 0; f < F_; f++) {
        float zi = g_zx[zxb + ((size_t)(f         ) << 12)] + g_zs[zsb + ((size_t)(f         ) << 12)];
        float zf = g_zx[zxb + ((size_t)(f +    F_ ) << 12)] + g_zs[zsb + ((size_t)(f +    F_ ) << 12)];
        float zc = g_zx[zxb + ((size_t)(f + 2 * F_) << 12)] + g_zs[zsb + ((size_t)(f + 2 * F_) << 12)];
        float zo = g_zx[zxb + ((size_t)(f + 3 * F_) << 12)] + g_zs[zsb + ((size_t)(f + 3 * F_) << 12)];

        float ig = __saturatef(fmaf(0.2f, zi, 0.5f));
        float fg = __saturatef(fmaf(0.2f, zf, 0.5f));
        float og = __saturatef(fmaf(0.2f, zo, 0.5f));

        float cold = g_c[cb + ((size_t)f << 12)];
        float cnew = fmaf(fg, cold, ig * tanhf(zc));
        float h    = og * tanhf(cnew);

        g_c[cb + ((size_t)f << 12)] = cnew;
        bf16 hi = __float2bfloat16(h);
        hh[f] = hi;
        hl[f] = __float2bfloat16(h - __bfloat162float(hi));
        op[f] = op[f] + h;
    }
}

// ------------------------- launch -------------------------------------------
extern "C" void kernel_launch(void* const* d_in, const int* in_sizes, int n_in,
                              void* d_out, int out_size) {
    const float* x  = (const float*)d_in[0];
    const float* Wx = (const float*)d_in[1];
    const float* Wh = (const float*)d_in[2];
    const float* b  = (const float*)d_in[3];
    const float* Wp = (const float*)d_in[4];
    const float* bp = (const float*)d_in[5];
    float* out = (float*)d_out;

    cudaFuncSetAttribute(gemm_mma_kernel, cudaFuncAttributeMaxDynamicSharedMemorySize, SM_BYTES);

    zero_state_kernel<<<4096, 256>>>();
    pack_wx_kernel<<<(COUT * KPAD_X) / 256, 256>>>(Wx);
    pack_wh_kernel<<<(COUT * KPAD_H) / 256, 256>>>(Wh);
    im2col_x_kernel<<<dim3(1024, 10), 256>>>(x);
    residual_kernel<<<(FRAMES * HW) / 256, 256>>>(x, Wp, bp, out);

    bf16 *Axh, *Axl, *Ahh, *Ahl, *Wxh, *Wxl, *Whh, *Whl;
    float *zx, *zs;
    cudaGetSymbolAddress((void**)&Axh, g_Ax_hi);
    cudaGetSymbolAddress((void**)&Axl, g_Ax_lo);
    cudaGetSymbolAddress((void**)&Ahh, g_Ah_hi);
    cudaGetSymbolAddress((void**)&Ahl, g_Ah_lo);
    cudaGetSymbolAddress((void**)&Wxh, g_Wx_hi);
    cudaGetSymbolAddress((void**)&Wxl, g_Wx_lo);
    cudaGetSymbolAddress((void**)&Whh, g_Wh_hi);
    cudaGetSymbolAddress((void**)&Whl, g_Wh_lo);
    cudaGetSymbolAddress((void**)&zx, g_zx);
    cudaGetSymbolAddress((void**)&zs, g_zs);

    // x-conv: M=262144, K=320 (5 chunks)
    gemm_mma_kernel<<<dim3(2048, 2), 256, SM_BYTES>>>(Axh, Axl, Wxh, Wxl, zx, b, 5, KPAD_X);

    for (int t = 0; t < T_; t++) {
        im2col_h_kernel<<<dim3(64, 9), 256>>>();
        gemm_mma_kernel<<<dim3(128, 2), 256, SM_BYTES>>>(Ahh, Ahl, Whh, Whl, zs, nullptr, 9, KPAD_H);
        gate_kernel<<<64, 256>>>(out, t);
    }
}

// round 7
// speedup vs baseline: 2.1393x; 2.1393x over previous
#include <cuda_runtime.h>
#include <cmath>

// ---------------------------------------------------------------------------
// ResidualConvLSTM2D  (B=4, T=16, H=W=64, Cin=32, F=64)
// Round 6: FFMA2 SIMT champion + bigger scheduling window + parallel gates.
// (tensor path dead on this harness: tcgen05 blocked by compute_103 PTX
//  target; classic mma.sync measured at ~FFMA2 rate on sm_103a.)
// ---------------------------------------------------------------------------

#define B_   4
#define T_   16
#define HH   64
#define WW   64
#define HW   4096
#define CIN_X 32
#define F_   64
#define COUT 256
#define FRAMES 64

typedef unsigned long long u64;

#define FMA_F32X2(d, a, b, c) \
    asm("fma.rn.f32x2 %0, %1, %2, %3;" : "=l"(d) : "l"(a), "l"(b), "l"(c))

__device__ __forceinline__ u64 bcast_f32x2(float v) {
    u64 r; unsigned u = __float_as_uint(v);
    asm("mov.b64 %0, {%1, %1};" : "=l"(r) : "r"(u));
    return r;
}
__device__ __forceinline__ void unpack_f32x2(u64 v, float& lo, float& hi) {
    unsigned a, b;
    asm("mov.b64 {%0, %1}, %2;" : "=r"(a), "=r"(b) : "l"(v));
    lo = __uint_as_float(a); hi = __uint_as_float(b);
}

// Scratch (allocation-free rule: __device__ globals)
__device__ float g_xplanar[FRAMES * CIN_X * HW];
__device__ float g_zx[FRAMES * COUT * HW];         // [frame][oc][pix]
__device__ float g_zs[B_ * COUT * HW];             // [b][oc][pix]
__device__ float g_h [B_ * F_ * HW];               // [b][f][pix]
__device__ float g_c [B_ * F_ * HW];               // [b][f][pix]

// ---------------------------------------------------------------------------
__global__ void zero_hc_kernel() {
    int g = blockIdx.x * 256 + threadIdx.x;
    if (g < B_ * F_ * HW) { g_h[g] = 0.f; g_c[g] = 0.f; }
}

// ---------------------------------------------------------------------------
// Pack x: NHWC -> planar [frame][ci][pix] via padded smem transpose.
// ---------------------------------------------------------------------------
__global__ void pack_x_kernel(const float* __restrict__ x) {
    __shared__ float s[256 * 33];
    int frame = blockIdx.y;
    int pix0  = blockIdx.x * 256;
    const float* src = x + (size_t)frame * (HW * CIN_X) + (size_t)pix0 * CIN_X;
    for (int i = threadIdx.x; i < 256 * CIN_X; i += 256) {
        int p = i >> 5, ci = i & 31;
        s[p * 33 + ci] = src[i];
    }
    __syncthreads();
    for (int i = threadIdx.x; i < 256 * CIN_X; i += 256) {
        int p = i & 255, ci = i >> 8;
        g_xplanar[((size_t)frame * CIN_X + ci) * HW + pix0 + p] = s[p * 33 + ci];
    }
}

// ---------------------------------------------------------------------------
// Residual: out[frame][pix][f] = x @ Wp + bp  (initializes all of d_out)
// ---------------------------------------------------------------------------
__global__ void residual_kernel(const float* __restrict__ x,
                                const float* __restrict__ Wp,
                                const float* __restrict__ bp,
                                float* __restrict__ out) {
    __shared__ float sW[CIN_X * F_];
    __shared__ float sb[F_];
    for (int i = threadIdx.x; i < CIN_X * F_; i += 256) sW[i] = Wp[i];
    if (threadIdx.x < F_) sb[threadIdx.x] = bp[threadIdx.x];
    __syncthreads();

    int g = blockIdx.x * 256 + threadIdx.x;
    float xv[CIN_X];
    const float4* xp = (const float4*)(x + (size_t)g * CIN_X);
    #pragma unroll
    for (int i = 0; i < CIN_X / 4; i++) {
        float4 v = xp[i];
        xv[4*i] = v.x; xv[4*i+1] = v.y; xv[4*i+2] = v.z; xv[4*i+3] = v.w;
    }
    float* op = out + (size_t)g * F_;
    #pragma unroll 4
    for (int f = 0; f < F_; f++) {
        float a = sb[f];
        #pragma unroll
        for (int ci = 0; ci < CIN_X; ci++)
            a = fmaf(xv[ci], sW[ci * F_ + f], a);
        op[f] = a;
    }
}

// ---------------------------------------------------------------------------
// 3x3 SAME conv, planar, FFMA2.  dy-outer loop (unroll 1), ci x dx fully
// unrolled: ~24 independent load/FMA groups per dy for latency hiding.
// Block 256 thr = 32x8; tile 32x16 pixels; 32 oc/block.
// ---------------------------------------------------------------------------
template<int CIN, int MODE>
__global__ __launch_bounds__(256, 2)
void conv3x3_kernel(const float* __restrict__ wsrc, const float* __restrict__ bias) {
    __shared__ float s_in[8 * 18 * 34];
    __shared__ float s_w [9 * 8 * 32];

    const float* in  = (MODE == 0) ? g_xplanar : g_h;
    float*       out = (MODE == 0) ? g_zx      : g_zs;

    int tileX = blockIdx.x & 1;
    int tileY = blockIdx.x >> 1;
    int frame = blockIdx.y;
    int oc0   = blockIdx.z * 32;
    int tid   = threadIdx.x;
    int tx = tid & 31, ty = tid >> 5;
    int gx0 = tileX * 32, gy0 = tileY * 16;

    u64 acc0[16], acc1[16];
    #pragma unroll
    for (int i = 0; i < 16; i++) { acc0[i] = 0ull; acc1[i] = 0ull; }

    for (int c0 = 0; c0 < CIN; c0 += 8) {
        for (int i = tid; i < 8 * 18 * 34; i += 256) {
            int xx = i % 34; int r = i / 34; int yy = r % 18; int ci = r / 18;
            int gy = gy0 + yy - 1, gx = gx0 + xx - 1;
            float v = 0.f;
            if ((unsigned)gy < 64u && (unsigned)gx < 64u)
                v = in[(((size_t)frame * CIN + c0 + ci) << 12) + gy * WW + gx];
            s_in[i] = v;
        }
        for (int i = tid; i < 9 * 8 * 32; i += 256) {
            int oc = i & 31, ci = (i >> 5) & 7, tap = i >> 8;
            s_w[i] = wsrc[(size_t)(tap * CIN + c0 + ci) * COUT + oc0 + oc];
        }
        __syncthreads();

        #pragma unroll 1
        for (int dy = 0; dy < 3; dy++) {
            #pragma unroll
            for (int ci = 0; ci < 8; ci++) {
                const float* r0 = &s_in[(ci * 18 + ty     + dy) * 34 + tx];
                const float* r1 = &s_in[(ci * 18 + ty + 8 + dy) * 34 + tx];
                #pragma unroll
                for (int dx = 0; dx < 3; dx++) {
                    u64 i0 = bcast_f32x2(r0[dx]);
                    u64 i1 = bcast_f32x2(r1[dx]);
                    const ulonglong2* wp = (const ulonglong2*)&s_w[((dy * 3 + dx) * 8 + ci) * 32];
                    #pragma unroll
                    for (int j = 0; j < 8; j++) {
                        ulonglong2 w2 = wp[j];
                        FMA_F32X2(acc0[2*j  ], i0, w2.x, acc0[2*j  ]);
                        FMA_F32X2(acc0[2*j+1], i0, w2.y, acc0[2*j+1]);
                        FMA_F32X2(acc1[2*j  ], i1, w2.x, acc1[2*j  ]);
                        FMA_F32X2(acc1[2*j+1], i1, w2.y, acc1[2*j+1]);
                    }
                }
            }
        }
        __syncthreads();
    }

    int p0 = (gy0 + ty) * WW + gx0 + tx;
    int p1 = p0 + 8 * WW;
    size_t obase = ((size_t)frame * COUT + oc0) << 12;
    #pragma unroll
    for (int j = 0; j < 16; j++) {
        float a0lo, a0hi, a1lo, a1hi;
        unpack_f32x2(acc0[j], a0lo, a0hi);
        unpack_f32x2(acc1[j], a1lo, a1hi);
        int oce = 2 * j, oco = 2 * j + 1;
        float bve = (MODE == 0) ? bias[oc0 + oce] : 0.f;
        float bvo = (MODE == 0) ? bias[oc0 + oco] : 0.f;
        out[obase + ((size_t)oce << 12) + p0] = a0lo + bve;
        out[obase + ((size_t)oco << 12) + p0] = a0hi + bvo;
        out[obase + ((size_t)oce << 12) + p1] = a1lo + bve;
        out[obase + ((size_t)oco << 12) + p1] = a1hi + bvo;
    }
}

// ---------------------------------------------------------------------------
// Gates + state + residual add.  4 f per thread, pix-fastest (coalesced).
// grid 1024 x 256 = 262144 threads.
// ---------------------------------------------------------------------------
__global__ void gate_kernel(float* __restrict__ out, int t) {
    int g   = blockIdx.x * 256 + threadIdx.x;   // < 262144
    int pix = g & 4095;
    int fg  = (g >> 12) & 15;
    int b   = g >> 16;
    int f0  = fg * 4;
    int frame = b * T_ + t;

    size_t zxb = (((size_t)frame * COUT) << 12) + pix;
    size_t zsb = (((size_t)b * COUT) << 12) + pix;
    size_t cb  = (((size_t)b * F_)   << 12) + pix;
    float* op  = out + (((size_t)frame << 12) + pix) * F_;

    #pragma unroll
    for (int j = 0; j < 4; j++) {
        int f = f0 + j;
        float zi = g_zx[zxb + ((size_t)(f         ) << 12)] + g_zs[zsb + ((size_t)(f         ) << 12)];
        float zf = g_zx[zxb + ((size_t)(f +    F_ ) << 12)] + g_zs[zsb + ((size_t)(f +    F_ ) << 12)];
        float zc = g_zx[zxb + ((size_t)(f + 2 * F_) << 12)] + g_zs[zsb + ((size_t)(f + 2 * F_) << 12)];
        float zo = g_zx[zxb + ((size_t)(f + 3 * F_) << 12)] + g_zs[zsb + ((size_t)(f + 3 * F_) << 12)];

        float ig = __saturatef(fmaf(0.2f, zi, 0.5f));
        float fg2 = __saturatef(fmaf(0.2f, zf, 0.5f));
        float og = __saturatef(fmaf(0.2f, zo, 0.5f));

        float cold = g_c[cb + ((size_t)f << 12)];
        float cnew = fmaf(fg2, cold, ig * tanhf(zc));
        float h    = og * tanhf(cnew);

        g_c[cb + ((size_t)f << 12)] = cnew;
        g_h[cb + ((size_t)f << 12)] = h;
        op[f] = op[f] + h;
    }
}

// ---------------------------------------------------------------------------
extern "C" void kernel_launch(void* const* d_in, const int* in_sizes, int n_in,
                              void* d_out, int out_size) {
    const float* x  = (const float*)d_in[0];
    const float* Wx = (const float*)d_in[1];
    const float* Wh = (const float*)d_in[2];
    const float* b  = (const float*)d_in[3];
    const float* Wp = (const float*)d_in[4];
    const float* bp = (const float*)d_in[5];
    float* out = (float*)d_out;

    zero_hc_kernel<<<(B_ * F_ * HW + 255) / 256, 256>>>();
    pack_x_kernel<<<dim3(16, FRAMES), 256>>>(x);
    residual_kernel<<<(FRAMES * HW) / 256, 256>>>(x, Wp, bp, out);
    conv3x3_kernel<CIN_X, 0><<<dim3(8, FRAMES, 8), 256>>>(Wx, b);

    for (int t = 0; t < T_; t++) {
        conv3x3_kernel<F_, 1><<<dim3(8, B_, 8), 256>>>(Wh, nullptr);
        gate_kernel<<<1024, 256>>>(out, t);
    }
}